// round 1
// baseline (speedup 1.0000x reference)
#include <cuda_runtime.h>
#include <cstdint>

#define FULLMASK 0xffffffffu
#define NEG_BIG  (-3.402823466e38f)

// Scratch (device globals — no allocation allowed)
__device__ float g_feat[32 * 2048];        // [b][2048]  (pos | neg features)
__device__ float g_part[16 * 32 * 1024];   // [kg][b][c] split-K partials

// ---------------------------------------------------------------------------
// Warp-collective: pop the 16 largest values from the union of per-lane lists
// v[N] (unsorted). Returns their sum on all lanes; optionally stores the 16
// values (lane 0 writes). Deterministic tie-break via lowest lane.
// ---------------------------------------------------------------------------
template <int N>
__device__ __forceinline__ float pop16_max_sum(float (&v)[N], float* store) {
    float sum = 0.f;
    const int lane = threadIdx.x & 31;
    #pragma unroll
    for (int r = 0; r < 16; ++r) {
        float c = v[0];
        #pragma unroll
        for (int s = 1; s < N; ++s) c = fmaxf(c, v[s]);
        float m = c;
        #pragma unroll
        for (int o = 16; o; o >>= 1) m = fmaxf(m, __shfl_xor_sync(FULLMASK, m, o));
        sum += m;
        unsigned ball = __ballot_sync(FULLMASK, c == m);
        if (lane == __ffs(ball) - 1) {
            bool done = false;
            #pragma unroll
            for (int s = 0; s < N; ++s)
                if (!done && v[s] == m) { v[s] = NEG_BIG; done = true; }
        }
        if (store != nullptr && lane == 0) store[r] = m;
    }
    return sum;
}

// ---------------------------------------------------------------------------
// Kernel 1: per batch row, compute ||f_rad||, ||f_histo||, top16/bottom16
// means of normalized histo row, then emit feat[b][0:1024]=pos, [1024:2048]=neg.
// grid 32, block 256.
// ---------------------------------------------------------------------------
__global__ void k1_stats_feat(const float* __restrict__ f_rad,
                              const float* __restrict__ f_histo) {
    const int b    = blockIdx.x;
    const int tid  = threadIdx.x;
    const int lane = tid & 31;
    const int wid  = tid >> 5;
    const float* __restrict__ hrow = f_histo + b * 2048;
    const float* __restrict__ rrow = f_rad   + b * 1024;

    __shared__ float s_redh[8], s_redr[8];
    __shared__ float s_top[128], s_bot[128];
    __shared__ float s_bcast[3];

    // --- sums of squares (both rows) + stage histo values in registers ---
    float ssh = 0.f, ssr = 0.f;
    float hv[8];
    #pragma unroll
    for (int t = 0; t < 8; ++t) {
        float v = hrow[wid * 256 + 32 * t + lane];
        hv[t] = v;
        ssh += v * v;
    }
    #pragma unroll
    for (int t = 0; t < 4; ++t) {
        float v = rrow[tid + 256 * t];
        ssr += v * v;
    }
    #pragma unroll
    for (int o = 16; o; o >>= 1) {
        ssh += __shfl_xor_sync(FULLMASK, ssh, o);
        ssr += __shfl_xor_sync(FULLMASK, ssr, o);
    }
    if (lane == 0) { s_redh[wid] = ssh; s_redr[wid] = ssr; }

    // --- per-warp top16 of h and of -h (bottom16) over its 256 elements ---
    float nv[8];
    #pragma unroll
    for (int t = 0; t < 8; ++t) nv[t] = -hv[t];
    pop16_max_sum<8>(hv, &s_top[wid * 16]);
    pop16_max_sum<8>(nv, &s_bot[wid * 16]);
    __syncthreads();

    // --- warp 0 merges the 8x16 candidates to the global top/bottom sums ---
    if (wid == 0) {
        float a[4], c[4];
        #pragma unroll
        for (int j = 0; j < 4; ++j) {
            a[j] = s_top[lane * 4 + j];
            c[j] = s_bot[lane * 4 + j];
        }
        float topsum = pop16_max_sum<4>(a, nullptr);
        float negbot = pop16_max_sum<4>(c, nullptr);
        if (lane == 0) {
            float th = 0.f, tr = 0.f;
            #pragma unroll
            for (int w = 0; w < 8; ++w) { th += s_redh[w]; tr += s_redr[w]; }
            float nh = fmaxf(sqrtf(th), 1e-12f);
            float nr = fmaxf(sqrtf(tr), 1e-12f);
            s_bcast[0] = 1.f / nr;
            s_bcast[1] = topsum / (16.f * nh);   // T  = mean(top16(h_norm))
            s_bcast[2] = -negbot / (16.f * nh);  // Bt = mean(bottom16(h_norm))
        }
    }
    __syncthreads();

    const float inv_nr = s_bcast[0];
    const float T      = s_bcast[1];
    const float Bt     = s_bcast[2];
    float* __restrict__ fout = g_feat + b * 2048;
    #pragma unroll
    for (int t = 0; t < 4; ++t) {
        int   i  = tid + 256 * t;
        float rv = rrow[i] * inv_nr;
        float p, n;
        if (rv >= 0.f) { p = rv * T;  n = -rv * Bt; }
        else           { p = rv * Bt; n = -rv * T;  }
        fout[i]        = p;
        fout[1024 + i] = n;
    }
}

// ---------------------------------------------------------------------------
// Kernel 2: split-K fp32 GEMM partials.  emb_part[kg][b][c] over K slice of 128.
// grid (32 cblk, 16 kg), block 64. Block tile 32b x 32c x 128k,
// thread tile 4b x 4c, float4 smem loads (stride 132 = 16B aligned).
// ---------------------------------------------------------------------------
__global__ void __launch_bounds__(64) k2_gemm(const float* __restrict__ W) {
    __shared__ float Ws[32 * 132];
    __shared__ float Fs[32 * 132];
    const int tid  = threadIdx.x;
    const int cblk = blockIdx.x;   // 0..31
    const int kg   = blockIdx.y;   // 0..15
    const int k0   = kg * 128;

    // Load W[32c][128k] and feat[32b][128k] tiles (float4, coalesced).
    #pragma unroll
    for (int it = 0; it < 16; ++it) {
        int idx = tid + it * 64;     // float4 id 0..1023
        int r   = idx >> 5;          // 0..31
        int kq  = idx & 31;          // 0..31
        float4 wv = *(const float4*)&W[(cblk * 32 + r) * 2048 + k0 + kq * 4];
        float4 fv = *(const float4*)&g_feat[r * 2048 + k0 + kq * 4];
        *(float4*)&Ws[r * 132 + kq * 4] = wv;
        *(float4*)&Fs[r * 132 + kq * 4] = fv;
    }
    __syncthreads();

    const int bt = tid & 7;    // b tile: rows 4*bt..4*bt+3
    const int ct = tid >> 3;   // c tile: cols 4*ct..4*ct+3
    float acc[4][4];
    #pragma unroll
    for (int i = 0; i < 4; ++i)
        #pragma unroll
        for (int j = 0; j < 4; ++j) acc[i][j] = 0.f;

    #pragma unroll 4
    for (int k = 0; k < 128; k += 4) {
        float4 f[4], w[4];
        #pragma unroll
        for (int i = 0; i < 4; ++i) f[i] = *(const float4*)&Fs[(4 * bt + i) * 132 + k];
        #pragma unroll
        for (int j = 0; j < 4; ++j) w[j] = *(const float4*)&Ws[(4 * ct + j) * 132 + k];
        #pragma unroll
        for (int i = 0; i < 4; ++i)
            #pragma unroll
            for (int j = 0; j < 4; ++j) {
                acc[i][j] += f[i].x * w[j].x;
                acc[i][j] += f[i].y * w[j].y;
                acc[i][j] += f[i].z * w[j].z;
                acc[i][j] += f[i].w * w[j].w;
            }
    }

    float* __restrict__ outp = g_part + kg * (32 * 1024) + cblk * 32;
    #pragma unroll
    for (int i = 0; i < 4; ++i) {
        float4 o = make_float4(acc[i][0], acc[i][1], acc[i][2], acc[i][3]);
        *(float4*)&outp[(4 * bt + i) * 1024 + 4 * ct] = o;
    }
}

// ---------------------------------------------------------------------------
// Kernel 3: reduce split-K partials + bias + token * flag.  grid 32, block 256
// (one float4 output per thread).
// ---------------------------------------------------------------------------
__global__ void k3_reduce(const float* __restrict__ bias,
                          const float* __restrict__ token,
                          const unsigned char* __restrict__ rad_mask,
                          const unsigned char* __restrict__ histo_mask,
                          float* __restrict__ out) {
    int gid = blockIdx.x * 256 + threadIdx.x;   // float4 id 0..8191
    int b   = gid >> 8;                         // 256 float4 per batch row
    int c4  = gid & 255;

    float4 acc = *(const float4*)&bias[c4 * 4];
    #pragma unroll
    for (int g = 0; g < 16; ++g) {
        float4 p = *(const float4*)&g_part[g * 32768 + b * 1024 + c4 * 4];
        acc.x += p.x; acc.y += p.y; acc.z += p.z; acc.w += p.w;
    }
    float flag = (rad_mask[b] != 0 && histo_mask[b] != 0) ? 0.f : 1.f;
    float4 tk  = *(const float4*)&token[c4 * 4];
    acc.x += tk.x * flag; acc.y += tk.y * flag;
    acc.z += tk.z * flag; acc.w += tk.w * flag;
    *(float4*)&out[b * 1024 + c4 * 4] = acc;
}

// ---------------------------------------------------------------------------
extern "C" void kernel_launch(void* const* d_in, const int* in_sizes, int n_in,
                              void* d_out, int out_size) {
    const float*         f_rad      = (const float*)d_in[0];
    const float*         f_histo    = (const float*)d_in[1];
    const unsigned char* rad_mask   = (const unsigned char*)d_in[2];
    const unsigned char* histo_mask = (const unsigned char*)d_in[3];
    const float*         W          = (const float*)d_in[4];
    const float*         bias       = (const float*)d_in[5];
    const float*         token      = (const float*)d_in[6];
    float*               out        = (float*)d_out;

    k1_stats_feat<<<32, 256>>>(f_rad, f_histo);
    k2_gemm<<<dim3(32, 16), 64>>>(W);
    k3_reduce<<<32, 256>>>(bias, token, rad_mask, histo_mask, out);
}

// round 2
// speedup vs baseline: 1.4743x; 1.4743x over previous
#include <cuda_runtime.h>
#include <cstdint>

#define FULLMASK 0xffffffffu

// Scratch (device globals — no allocation allowed)
__device__ float g_feat[32 * 2048];        // [b][2048]  (pos | neg features)
__device__ float g_part[32 * 32 * 1024];   // [kg][b][c] split-K partials

// Monotone float -> uint key (ascending). key(-f) == ~key(f).
__device__ __forceinline__ unsigned key_encode(float f) {
    unsigned u = __float_as_uint(f);
    return (u & 0x80000000u) ? ~u : (u | 0x80000000u);
}
__device__ __forceinline__ float key_decode(unsigned k) {
    unsigned u = (k & 0x80000000u) ? (k & 0x7fffffffu) : ~k;
    return __uint_as_float(u);
}

// ---------------------------------------------------------------------------
// Kernel 1: per batch row b — row norms + exact top-16/bottom-16 sums of the
// histo row via MSB-first 8-bit radix select (2 selections concurrently),
// then emit feat[b] = [pos(1024) | neg(1024)].  grid 32, block 256.
// ---------------------------------------------------------------------------
__global__ void __launch_bounds__(256) k1_stats_feat(
        const float* __restrict__ f_rad, const float* __restrict__ f_histo) {
    const int b    = blockIdx.x;
    const int tid  = threadIdx.x;
    const int lane = tid & 31;
    const int wid  = tid >> 5;
    const float* __restrict__ hrow = f_histo + b * 2048;
    const float* __restrict__ rrow = f_rad   + b * 1024;

    __shared__ unsigned hist[2][256];
    __shared__ unsigned sh_prefix[2];
    __shared__ unsigned sh_rem[2];
    __shared__ float    s_red[4][8];
    __shared__ float    s_bcast[3];

    // Load histo row (8/thread) + rad row (4/thread), sums of squares.
    float hv[8];
    float ssh = 0.f, ssr = 0.f;
    #pragma unroll
    for (int u = 0; u < 8; ++u) {
        float v = hrow[u * 256 + tid];
        hv[u] = v;
        ssh += v * v;
    }
    #pragma unroll
    for (int u = 0; u < 4; ++u) {
        float v = rrow[u * 256 + tid];
        ssr += v * v;
    }

    unsigned keys[8];
    #pragma unroll
    for (int u = 0; u < 8; ++u) keys[u] = key_encode(hv[u]);

    if (tid < 2) { sh_prefix[tid] = 0u; sh_rem[tid] = 16u; }

    // ---- 4 radix passes, MSB byte first ----
    #pragma unroll
    for (int p = 3; p >= 0; --p) {
        const int shift = 8 * p;
        const unsigned mhi = (p == 3) ? 0u : (0xFFFFFFFFu << (shift + 8));

        hist[0][tid] = 0u;
        hist[1][tid] = 0u;
        __syncthreads();

        const unsigned pfx0 = sh_prefix[0];
        const unsigned pfx1 = sh_prefix[1];
        #pragma unroll
        for (int u = 0; u < 8; ++u) {
            unsigned k  = keys[u];
            unsigned kn = ~k;
            if ((k  & mhi) == pfx0) atomicAdd(&hist[0][(k  >> shift) & 255u], 1u);
            if ((kn & mhi) == pfx1) atomicAdd(&hist[1][(kn >> shift) & 255u], 1u);
        }
        __syncthreads();

        if (wid < 2) {
            const int s = wid;
            const unsigned rem = sh_rem[s];
            unsigned c[8], Sl = 0u;
            #pragma unroll
            for (int j = 0; j < 8; ++j) { c[j] = hist[s][lane * 8 + j]; Sl += c[j]; }
            // inclusive suffix sum over lanes (lanes >= l)
            unsigned incl = Sl;
            #pragma unroll
            for (int o = 1; o < 32; o <<= 1) {
                unsigned v = __shfl_down_sync(FULLMASK, incl, o);
                if (lane + o < 32) incl += v;
            }
            unsigned cum = incl - Sl;   // count of elements in strictly higher lanes
            #pragma unroll
            for (int j = 7; j >= 0; --j) {
                // cum == count of keys with byte > (lane*8+j) under current prefix
                if (cum < rem && cum + c[j] >= rem) {
                    sh_prefix[s] |= (unsigned)(lane * 8 + j) << shift;
                    sh_rem[s]     = rem - cum;
                }
                cum += c[j];
            }
        }
        __syncthreads();
    }

    const unsigned t0 = sh_prefix[0], rem0 = sh_rem[0];
    const unsigned t1 = sh_prefix[1], rem1 = sh_rem[1];

    // Sums of strictly-greater elements for each selection.
    float sum0 = 0.f, sum1 = 0.f;
    #pragma unroll
    for (int u = 0; u < 8; ++u) {
        if (keys[u] > t0)   sum0 += hv[u];
        if ((~keys[u]) > t1) sum1 += (-hv[u]);
    }

    // Block-reduce {ssh, ssr, sum0, sum1}
    #pragma unroll
    for (int o = 16; o; o >>= 1) {
        ssh  += __shfl_xor_sync(FULLMASK, ssh,  o);
        ssr  += __shfl_xor_sync(FULLMASK, ssr,  o);
        sum0 += __shfl_xor_sync(FULLMASK, sum0, o);
        sum1 += __shfl_xor_sync(FULLMASK, sum1, o);
    }
    if (lane == 0) {
        s_red[0][wid] = ssh;  s_red[1][wid] = ssr;
        s_red[2][wid] = sum0; s_red[3][wid] = sum1;
    }
    __syncthreads();
    if (tid == 0) {
        float a0 = 0.f, a1 = 0.f, a2 = 0.f, a3 = 0.f;
        #pragma unroll
        for (int w = 0; w < 8; ++w) {
            a0 += s_red[0][w]; a1 += s_red[1][w];
            a2 += s_red[2][w]; a3 += s_red[3][w];
        }
        float nh  = fmaxf(sqrtf(a0), 1e-12f);
        float nr  = fmaxf(sqrtf(a1), 1e-12f);
        float top = a2 + (float)rem0 * key_decode(t0);   // sum of top16(h)
        float bng = a3 + (float)rem1 * key_decode(t1);   // sum of top16(-h)
        s_bcast[0] = 1.f / nr;
        s_bcast[1] = top  / (16.f * nh);    // T  = mean(top16(h_norm))
        s_bcast[2] = -bng / (16.f * nh);    // Bt = mean(bottom16(h_norm))
    }
    __syncthreads();

    const float inv_nr = s_bcast[0];
    const float T      = s_bcast[1];
    const float Bt     = s_bcast[2];
    float* __restrict__ fout = g_feat + b * 2048;
    #pragma unroll
    for (int u = 0; u < 4; ++u) {
        int   i  = u * 256 + tid;
        float rv = rrow[i] * inv_nr;
        float pm, nm;
        if (rv >= 0.f) { pm = rv * T;  nm = -rv * Bt; }
        else           { pm = rv * Bt; nm = -rv * T;  }
        fout[i]        = pm;
        fout[1024 + i] = nm;
    }
}

// ---------------------------------------------------------------------------
// Kernel 2: split-K fp32 GEMM partials. Block tile 32b x 64c x 64k, 32 threads,
// thread tile 8b x 8c. XOR-swizzled smem (conflict-free inner-loop reads).
// grid (16 cblk, 32 kg).
// ---------------------------------------------------------------------------
__global__ void __launch_bounds__(32) k2_gemm(const float* __restrict__ W) {
    __shared__ float Ws[64 * 64];
    __shared__ float Fs[32 * 64];
    const int tid = threadIdx.x;
    const int c0  = blockIdx.x * 64;
    const int kg  = blockIdx.y;
    const int k0  = kg * 64;

    // Load W tile 64c x 64k (coalesced float4 reads, swizzled scalar stores).
    #pragma unroll
    for (int it = 0; it < 32; ++it) {
        int idx = it * 32 + tid;          // 0..1023 float4 ids
        int r   = idx >> 4;               // 0..63
        int kq  = idx & 15;               // 0..15
        float4 v = *(const float4*)&W[(c0 + r) * 2048 + k0 + kq * 4];
        int sw = r >> 3;
        float* base = &Ws[r * 64];
        base[(kq * 4 + 0) ^ sw] = v.x;
        base[(kq * 4 + 1) ^ sw] = v.y;
        base[(kq * 4 + 2) ^ sw] = v.z;
        base[(kq * 4 + 3) ^ sw] = v.w;
    }
    // Load feat tile 32b x 64k.
    #pragma unroll
    for (int it = 0; it < 16; ++it) {
        int idx = it * 32 + tid;          // 0..511
        int r   = idx >> 4;               // 0..31
        int kq  = idx & 15;
        float4 v = *(const float4*)&g_feat[r * 2048 + k0 + kq * 4];
        int sw = r >> 3;
        float* base = &Fs[r * 64];
        base[(kq * 4 + 0) ^ sw] = v.x;
        base[(kq * 4 + 1) ^ sw] = v.y;
        base[(kq * 4 + 2) ^ sw] = v.z;
        base[(kq * 4 + 3) ^ sw] = v.w;
    }
    __syncthreads();

    const int bl = tid >> 3;   // 0..3  -> b rows 8*bl..+7
    const int cl = tid & 7;    // 0..7  -> c cols 8*cl..+7
    const float* __restrict__ fb = &Fs[(8 * bl) * 64];
    const float* __restrict__ wb = &Ws[(8 * cl) * 64];

    float acc[8][8];
    #pragma unroll
    for (int i = 0; i < 8; ++i)
        #pragma unroll
        for (int j = 0; j < 8; ++j) acc[i][j] = 0.f;

    #pragma unroll 4
    for (int k = 0; k < 64; ++k) {
        float fv[8], wv[8];
        const int kf = k ^ bl;
        const int kw = k ^ cl;
        #pragma unroll
        for (int i = 0; i < 8; ++i) fv[i] = fb[i * 64 + kf];
        #pragma unroll
        for (int j = 0; j < 8; ++j) wv[j] = wb[j * 64 + kw];
        #pragma unroll
        for (int i = 0; i < 8; ++i)
            #pragma unroll
            for (int j = 0; j < 8; ++j)
                acc[i][j] = fmaf(fv[i], wv[j], acc[i][j]);
    }

    float* __restrict__ outp = g_part + kg * (32 * 1024) + c0 + 8 * cl;
    #pragma unroll
    for (int i = 0; i < 8; ++i) {
        float4 o0 = make_float4(acc[i][0], acc[i][1], acc[i][2], acc[i][3]);
        float4 o1 = make_float4(acc[i][4], acc[i][5], acc[i][6], acc[i][7]);
        float* rp = outp + (8 * bl + i) * 1024;
        *(float4*)&rp[0] = o0;
        *(float4*)&rp[4] = o1;
    }
}

// ---------------------------------------------------------------------------
// Kernel 3: reduce 32 split-K partials + bias + token * flag. grid 32, blk 256.
// ---------------------------------------------------------------------------
__global__ void __launch_bounds__(256) k3_reduce(
        const float* __restrict__ bias, const float* __restrict__ token,
        const unsigned char* __restrict__ rad_mask,
        const unsigned char* __restrict__ histo_mask,
        float* __restrict__ out) {
    int gid = blockIdx.x * 256 + threadIdx.x;   // float4 id 0..8191
    int b   = gid >> 8;
    int c4  = gid & 255;

    float4 acc = *(const float4*)&bias[c4 * 4];
    #pragma unroll
    for (int g = 0; g < 32; ++g) {
        float4 p = *(const float4*)&g_part[g * 32768 + b * 1024 + c4 * 4];
        acc.x += p.x; acc.y += p.y; acc.z += p.z; acc.w += p.w;
    }
    float flag = (rad_mask[b] != 0 && histo_mask[b] != 0) ? 0.f : 1.f;
    float4 tk  = *(const float4*)&token[c4 * 4];
    acc.x += tk.x * flag; acc.y += tk.y * flag;
    acc.z += tk.z * flag; acc.w += tk.w * flag;
    *(float4*)&out[b * 1024 + c4 * 4] = acc;
}

// ---------------------------------------------------------------------------
extern "C" void kernel_launch(void* const* d_in, const int* in_sizes, int n_in,
                              void* d_out, int out_size) {
    const float*         f_rad      = (const float*)d_in[0];
    const float*         f_histo    = (const float*)d_in[1];
    const unsigned char* rad_mask   = (const unsigned char*)d_in[2];
    const unsigned char* histo_mask = (const unsigned char*)d_in[3];
    const float*         W          = (const float*)d_in[4];
    const float*         bias       = (const float*)d_in[5];
    const float*         token      = (const float*)d_in[6];
    float*               out        = (float*)d_out;

    k1_stats_feat<<<32, 256>>>(f_rad, f_histo);
    k2_gemm<<<dim3(16, 32), 32>>>(W);
    k3_reduce<<<32, 256>>>(bias, token, rad_mask, histo_mask, out);
}